// round 4
// baseline (speedup 1.0000x reference)
#include <cuda_runtime.h>
#include <cuda_bf16.h>
#include <stdint.h>

#define NNODES 100000
#define NEDGES 1600000
#define INCH   256
#define OUTCH  64
#define GN     128   // combined output cols (mu | logstd)

// ---------------- static scratch (no allocations allowed) ----------------
__device__ int    g_cnt[NNODES];           // incoming-edge count (excl. self loop)
__device__ int    g_off[NNODES];           // CSR offsets (exclusive scan of cnt)
__device__ int    g_cur[NNODES];           // build cursors
__device__ float  g_dinv[NNODES];          // rsqrt(deg) with self loop
__device__ int    g_perm[NEDGES];          // src indices grouped by dst
__device__ int    g_bsum[128];             // block sums for scan
__device__ int    g_is64;                  // 1 if edge_index is int64 on device
__device__ __align__(16) float4 g_hs[NNODES * 32];  // h * dinv[row], [N][128] as float4

// ---------------- edge index access helpers ----------------
__device__ __forceinline__ int clampN(int v) {
    v = v < 0 ? 0 : v;
    return v >= NNODES ? NNODES - 1 : v;
}
// e in [0, NEDGES): returns (src, dst) honoring runtime dtype flag
__device__ __forceinline__ int load_src(const int* w, int is64, int e) {
    return clampN(is64 ? w[2 * e] : w[e]);
}
__device__ __forceinline__ int load_dst(const int* w, int is64, int e) {
    return clampN(is64 ? w[2 * (NEDGES + e)] : w[NEDGES + e]);
}

// ---------------- kernels ----------------
// Detect int64 vs int32: for int64 (values < 2^31), odd int32 words are 0.
__global__ void probe_kernel(const int* __restrict__ w) {
    int tid = threadIdx.x;                  // 256 threads
    int v = w[2 * tid + 1];                 // odd words of first 512
    int allzero = __syncthreads_and(v == 0);
    if (tid == 0) g_is64 = allzero ? 1 : 0;
}

__global__ void zero_cnt_kernel() {
    int i = blockIdx.x * blockDim.x + threadIdx.x;
    if (i < NNODES) g_cnt[i] = 0;
}

__global__ void count_kernel(const int* __restrict__ w) {
    int e = blockIdx.x * blockDim.x + threadIdx.x;
    if (e < NEDGES) {
        int dst = load_dst(w, g_is64, e);
        atomicAdd(&g_cnt[dst], 1);
    }
}

// block-wise exclusive scan of g_cnt -> g_off (local), block totals -> g_bsum
__global__ void __launch_bounds__(1024) scan_block_kernel() {
    int tid = threadIdx.x;
    int i = blockIdx.x * 1024 + tid;
    int v = (i < NNODES) ? g_cnt[i] : 0;
    int lane = tid & 31, w = tid >> 5;
    int x = v;
    #pragma unroll
    for (int d = 1; d < 32; d <<= 1) {
        int y = __shfl_up_sync(0xffffffffu, x, d);
        if (lane >= d) x += y;
    }
    __shared__ int wsum[32];
    if (lane == 31) wsum[w] = x;
    __syncthreads();
    if (w == 0) {
        int y = wsum[lane];
        #pragma unroll
        for (int d = 1; d < 32; d <<= 1) {
            int z = __shfl_up_sync(0xffffffffu, y, d);
            if (lane >= d) y += z;
        }
        wsum[lane] = y;
    }
    __syncthreads();
    int incl = x + ((w > 0) ? wsum[w - 1] : 0);
    if (i < NNODES) g_off[i] = incl - v;          // local exclusive
    if (tid == 1023) g_bsum[blockIdx.x] = incl;   // block total
}

__global__ void scan_bsums_kernel(int nb) {
    __shared__ int s[128];
    int tid = threadIdx.x;
    if (tid < nb) s[tid] = g_bsum[tid];
    __syncthreads();
    if (tid == 0) {
        int acc = 0;
        for (int b = 0; b < nb; b++) { int t = s[b]; s[b] = acc; acc += t; }
    }
    __syncthreads();
    if (tid < nb) g_bsum[tid] = s[tid];
}

__global__ void scan_finalize_kernel() {
    int i = blockIdx.x * blockDim.x + threadIdx.x;
    if (i < NNODES) {
        int o = g_off[i] + g_bsum[i >> 10];
        g_off[i] = o;
        g_cur[i] = o;
        g_dinv[i] = rsqrtf((float)(g_cnt[i] + 1));   // +1 self loop; always > 0
    }
}

__global__ void build_perm_kernel(const int* __restrict__ w) {
    int e = blockIdx.x * blockDim.x + threadIdx.x;
    if (e < NEDGES) {
        int is64 = g_is64;
        int src = load_src(w, is64, e);
        int dst = load_dst(w, is64, e);
        int p = atomicAdd(&g_cur[dst], 1);
        if (p >= 0 && p < NEDGES) g_perm[p] = src;
    }
}

// fused dual GEMM: hs[n][0:64] = (x@W_mu)*dinv[n], hs[n][64:128] = (x@W_logstd)*dinv[n]
#define TM 64
#define TK 32
__global__ void __launch_bounds__(256) gemm_kernel(const float* __restrict__ x,
                                                   const float* __restrict__ Wmu,
                                                   const float* __restrict__ Wls) {
    __shared__ __align__(16) float xs[TM][TK];
    __shared__ __align__(16) float ws[TK][GN];
    int t  = threadIdx.x;
    int tx = t & 31;     // col group: cols tx*4 .. tx*4+3
    int ty = t >> 5;     // row group: rows ty*8 .. ty*8+7
    int m0 = blockIdx.x * TM;

    float4 acc[8];
    #pragma unroll
    for (int i = 0; i < 8; i++) acc[i] = make_float4(0.f, 0.f, 0.f, 0.f);

    for (int k0 = 0; k0 < INCH; k0 += TK) {
        // load x tile: 64 rows x 32 k
        #pragma unroll
        for (int j = 0; j < 2; j++) {
            int v = t + j * 256;              // 0..511 float4 slots
            int row = v >> 3;
            int kk  = (v & 7) << 2;
            float4 val = make_float4(0.f, 0.f, 0.f, 0.f);
            if (m0 + row < NNODES)
                val = *(const float4*)&x[(size_t)(m0 + row) * INCH + k0 + kk];
            *(float4*)&xs[row][kk] = val;
        }
        // load W tile: 32 k x 128 cols (mu | logstd)
        #pragma unroll
        for (int j = 0; j < 4; j++) {
            int v  = t + j * 256;             // 0..1023 float4 slots
            int kk = v >> 5;
            int c  = (v & 31) << 2;
            float4 wv;
            if (c < OUTCH) wv = *(const float4*)&Wmu[(k0 + kk) * OUTCH + c];
            else           wv = *(const float4*)&Wls[(k0 + kk) * OUTCH + (c - OUTCH)];
            *(float4*)&ws[kk][c] = wv;
        }
        __syncthreads();
        #pragma unroll
        for (int kk = 0; kk < TK; kk++) {
            float4 wv = *(const float4*)&ws[kk][tx << 2];
            #pragma unroll
            for (int i = 0; i < 8; i++) {
                float a = xs[ty * 8 + i][kk];
                acc[i].x += a * wv.x;
                acc[i].y += a * wv.y;
                acc[i].z += a * wv.z;
                acc[i].w += a * wv.w;
            }
        }
        __syncthreads();
    }
    #pragma unroll
    for (int i = 0; i < 8; i++) {
        int row = m0 + ty * 8 + i;
        if (row < NNODES) {
            float d = g_dinv[row];
            g_hs[(size_t)row * 32 + tx] =
                make_float4(acc[i].x * d, acc[i].y * d, acc[i].z * d, acc[i].w * d);
        }
    }
}

// warp-per-node gather: out = dinv[n] * (hs[n] + sum_{src in-edges} hs[src]) + bias
__global__ void __launch_bounds__(256) gather_kernel(const float* __restrict__ bmu,
                                                     const float* __restrict__ bls,
                                                     float* __restrict__ out) {
    int gw = (blockIdx.x * blockDim.x + threadIdx.x) >> 5;
    if (gw >= NNODES) return;
    int lane = threadIdx.x & 31;
    int n = gw;
    float din  = g_dinv[n];
    int begin  = g_off[n];
    int cn     = g_cnt[n];

    float4 acc = g_hs[(size_t)n * 32 + lane];   // self-loop term (hs already * dinv[n])
    for (int base = 0; base < cn; base += 32) {
        int idx = base + lane;
        int sp = (idx < cn) ? g_perm[begin + idx] : 0;
        int m = cn - base; if (m > 32) m = 32;
        for (int j = 0; j < m; j++) {
            int s = __shfl_sync(0xffffffffu, sp, j);
            float4 v = g_hs[(size_t)s * 32 + lane];
            acc.x += v.x; acc.y += v.y; acc.z += v.z; acc.w += v.w;
        }
    }
    float4* out4 = (float4*)out;
    if (lane < 16) {
        float4 bb = ((const float4*)bmu)[lane];
        out4[(size_t)n * 16 + lane] =
            make_float4(acc.x * din + bb.x, acc.y * din + bb.y,
                        acc.z * din + bb.z, acc.w * din + bb.w);
    } else {
        float4 bb = ((const float4*)bls)[lane - 16];
        out4[(size_t)NNODES * 16 + (size_t)n * 16 + (lane - 16)] =
            make_float4(acc.x * din + bb.x, acc.y * din + bb.y,
                        acc.z * din + bb.z, acc.w * din + bb.w);
    }
}

// ---------------- launch ----------------
extern "C" void kernel_launch(void* const* d_in, const int* in_sizes, int n_in,
                              void* d_out, int out_size) {
    const float* x   = (const float*)d_in[0];
    const int*   ew  = (const int*)d_in[1];     // edge_index words (int32 or int64, probed)
    const float* Wmu = (const float*)d_in[2];
    const float* bmu = (const float*)d_in[3];
    const float* Wls = (const float*)d_in[4];
    const float* bls = (const float*)d_in[5];
    float*       out = (float*)d_out;

    const int NB_N   = (NNODES + 255) / 256;
    const int NB_E   = (NEDGES + 255) / 256;
    const int NB_SC  = (NNODES + 1023) / 1024;     // 98
    const int NB_GM  = (NNODES + TM - 1) / TM;     // 1563
    const int NB_GA  = (NNODES * 32 + 255) / 256;  // 12500

    probe_kernel<<<1, 256>>>(ew);
    zero_cnt_kernel<<<NB_N, 256>>>();
    count_kernel<<<NB_E, 256>>>(ew);
    scan_block_kernel<<<NB_SC, 1024>>>();
    scan_bsums_kernel<<<1, 128>>>(NB_SC);
    scan_finalize_kernel<<<NB_N, 256>>>();
    gemm_kernel<<<NB_GM, 256>>>(x, Wmu, Wls);
    build_perm_kernel<<<NB_E, 256>>>(ew);
    gather_kernel<<<NB_GA, 256>>>(bmu, bls, out);
}

// round 7
// speedup vs baseline: 1.1588x; 1.1588x over previous
#include <cuda_runtime.h>
#include <cuda_bf16.h>
#include <stdint.h>

#define NNODES 100000
#define NEDGES 1600000
#define INCH   256
#define OUTCH  64
#define GN     128   // combined output cols (mu | logstd)

// ---------------- static scratch (no allocations allowed) ----------------
__device__ int    g_cnt[NNODES];
__device__ int    g_off[NNODES];
__device__ int    g_cur[NNODES];
__device__ float  g_dinv[NNODES];
__device__ int    g_perm[NEDGES];
__device__ int    g_bsum[128];
__device__ int    g_is64;
__device__ __align__(16) float4 g_hs[NNODES * 32];  // h * dinv[row], [N][128] as float4

// ---------------- edge index access helpers ----------------
__device__ __forceinline__ int clampN(int v) {
    v = v < 0 ? 0 : v;
    return v >= NNODES ? NNODES - 1 : v;
}
__device__ __forceinline__ int load_src(const int* w, int is64, int e) {
    return clampN(is64 ? w[2 * e] : w[e]);
}
__device__ __forceinline__ int load_dst(const int* w, int is64, int e) {
    return clampN(is64 ? w[2 * (NEDGES + e)] : w[NEDGES + e]);
}

// ---------------- kernels ----------------
__global__ void probe_kernel(const int* __restrict__ w) {
    int tid = threadIdx.x;
    int v = w[2 * tid + 1];
    int allzero = __syncthreads_and(v == 0);
    if (tid == 0) g_is64 = allzero ? 1 : 0;
}

__global__ void zero_cnt_kernel() {
    int i = blockIdx.x * blockDim.x + threadIdx.x;
    if (i < NNODES) g_cnt[i] = 0;
}

__global__ void count_kernel(const int* __restrict__ w) {
    int e = blockIdx.x * blockDim.x + threadIdx.x;
    if (e < NEDGES) atomicAdd(&g_cnt[load_dst(w, g_is64, e)], 1);
}

__global__ void __launch_bounds__(1024) scan_block_kernel() {
    int tid = threadIdx.x;
    int i = blockIdx.x * 1024 + tid;
    int v = (i < NNODES) ? g_cnt[i] : 0;
    int lane = tid & 31, w = tid >> 5;
    int x = v;
    #pragma unroll
    for (int d = 1; d < 32; d <<= 1) {
        int y = __shfl_up_sync(0xffffffffu, x, d);
        if (lane >= d) x += y;
    }
    __shared__ int wsum[32];
    if (lane == 31) wsum[w] = x;
    __syncthreads();
    if (w == 0) {
        int y = wsum[lane];
        #pragma unroll
        for (int d = 1; d < 32; d <<= 1) {
            int z = __shfl_up_sync(0xffffffffu, y, d);
            if (lane >= d) y += z;
        }
        wsum[lane] = y;
    }
    __syncthreads();
    int incl = x + ((w > 0) ? wsum[w - 1] : 0);
    if (i < NNODES) g_off[i] = incl - v;
    if (tid == 1023) g_bsum[blockIdx.x] = incl;
}

__global__ void scan_bsums_kernel(int nb) {
    __shared__ int s[128];
    int tid = threadIdx.x;
    if (tid < nb) s[tid] = g_bsum[tid];
    __syncthreads();
    if (tid == 0) {
        int acc = 0;
        for (int b = 0; b < nb; b++) { int t = s[b]; s[b] = acc; acc += t; }
    }
    __syncthreads();
    if (tid < nb) g_bsum[tid] = s[tid];
}

__global__ void scan_finalize_kernel() {
    int i = blockIdx.x * blockDim.x + threadIdx.x;
    if (i < NNODES) {
        int o = g_off[i] + g_bsum[i >> 10];
        g_off[i] = o;
        g_cur[i] = o;
        g_dinv[i] = rsqrtf((float)(g_cnt[i] + 1));
    }
}

__global__ void build_perm_kernel(const int* __restrict__ w) {
    int e = blockIdx.x * blockDim.x + threadIdx.x;
    if (e < NEDGES) {
        int is64 = g_is64;
        int src = load_src(w, is64, e);
        int dst = load_dst(w, is64, e);
        int p = atomicAdd(&g_cur[dst], 1);
        if (p >= 0 && p < NEDGES) g_perm[p] = src;
    }
}

// ---------------- HMMA (mma.sync) dual GEMM ----------------
// hs[n][0:64] = (x@W_mu)*dinv[n], hs[n][64:128] = (x@W_logstd)*dinv[n]
// bf16 hi/lo split: D = Ah*Bh + Ah*Bl + Al*Bh  (fp32 accumulate in registers)
#define MT 128
#define KC 64
#define NCHUNK (INCH / KC)   // 4
#define ASTR 72              // bf16 elements per SMEM row (144B: 4-bank shift/row -> conflict-free)
#define TILE_BYTES (128 * ASTR * 2)   // 18432

__device__ __forceinline__ uint32_t bf2pack(float a, float b) {
    __nv_bfloat162 p = __nv_bfloat162(__float2bfloat16_rn(a), __float2bfloat16_rn(b));
    return *(uint32_t*)&p;
}
// store hi & lo pair (cols c, c+1) for row r
__device__ __forceinline__ void split_store2(char* hi, char* lo, int r, int c,
                                             float a, float b) {
    float ha = __bfloat162float(__float2bfloat16_rn(a));
    float hb = __bfloat162float(__float2bfloat16_rn(b));
    *(uint32_t*)(hi + r * (ASTR * 2) + c * 2) = bf2pack(a, b);
    *(uint32_t*)(lo + r * (ASTR * 2) + c * 2) = bf2pack(a - ha, b - hb);
}
__device__ __forceinline__ uint32_t lds_pair(const char* base, int r, int c) {
    return *(const uint32_t*)(base + r * (ASTR * 2) + c * 2);
}
__device__ __forceinline__ void mma16816(float* d, const uint32_t* a, uint32_t b0, uint32_t b1) {
    asm volatile(
        "mma.sync.aligned.m16n8k16.row.col.f32.bf16.bf16.f32 "
        "{%0,%1,%2,%3}, {%4,%5,%6,%7}, {%8,%9}, {%0,%1,%2,%3};"
        : "+f"(d[0]), "+f"(d[1]), "+f"(d[2]), "+f"(d[3])
        : "r"(a[0]), "r"(a[1]), "r"(a[2]), "r"(a[3]), "r"(b0), "r"(b1));
}

__global__ void __launch_bounds__(256) gemm_mma_kernel(const float* __restrict__ x,
                                                       const float* __restrict__ Wmu,
                                                       const float* __restrict__ Wls) {
    extern __shared__ char dsm[];
    char* sAh = dsm;
    char* sAl = dsm + TILE_BYTES;
    char* sBh = dsm + 2 * TILE_BYTES;
    char* sBl = dsm + 3 * TILE_BYTES;

    int tid  = threadIdx.x;
    int wid  = tid >> 5, lane = tid & 31;
    int wm   = wid & 3;          // m strip: rows wm*32 .. +31
    int wn   = wid >> 2;         // n strip: cols wn*64 .. +63
    int g    = lane >> 2;        // 0..7
    int cq   = lane & 3;         // 0..3
    int m0   = blockIdx.x * MT;

    float acc[2][8][4];
    #pragma unroll
    for (int t = 0; t < 2; t++)
        #pragma unroll
        for (int n = 0; n < 8; n++)
            #pragma unroll
            for (int q = 0; q < 4; q++) acc[t][n][q] = 0.f;

    for (int c0 = 0; c0 < NCHUNK; c0++) {
        int k0 = c0 * KC;
        // ---- A chunk: row tid/2, half (tid&1)*32 (8 float4) ----
        {
            int r = tid >> 1, h = (tid & 1) * 32;
            int row = m0 + r;
            bool valid = row < NNODES;
            const float4* xr = (const float4*)&x[(size_t)(valid ? row : 0) * INCH + k0 + h];
            #pragma unroll
            for (int j = 0; j < 8; j++) {
                float4 v = valid ? xr[j] : make_float4(0.f, 0.f, 0.f, 0.f);
                split_store2(sAh, sAl, r, h + j * 4,     v.x, v.y);
                split_store2(sAh, sAl, r, h + j * 4 + 2, v.z, v.w);
            }
        }
        // ---- B chunk: B[n][k] = W[k0+k][n]; 4x4 transpose blocks ----
        #pragma unroll
        for (int it = 0; it < 2; it++) {
            int w  = tid + it * 256;        // 0..511
            int nq = w >> 4, kq = w & 15;
            int n0 = nq * 4, kc0 = kq * 4;
            const float* Wp = (n0 < OUTCH) ? Wmu : Wls;
            int ncol = (n0 < OUTCH) ? n0 : n0 - OUTCH;
            float4 a0 = *(const float4*)&Wp[(size_t)(k0 + kc0 + 0) * OUTCH + ncol];
            float4 a1 = *(const float4*)&Wp[(size_t)(k0 + kc0 + 1) * OUTCH + ncol];
            float4 a2 = *(const float4*)&Wp[(size_t)(k0 + kc0 + 2) * OUTCH + ncol];
            float4 a3 = *(const float4*)&Wp[(size_t)(k0 + kc0 + 3) * OUTCH + ncol];
            split_store2(sBh, sBl, n0 + 0, kc0,     a0.x, a1.x);
            split_store2(sBh, sBl, n0 + 0, kc0 + 2, a2.x, a3.x);
            split_store2(sBh, sBl, n0 + 1, kc0,     a0.y, a1.y);
            split_store2(sBh, sBl, n0 + 1, kc0 + 2, a2.y, a3.y);
            split_store2(sBh, sBl, n0 + 2, kc0,     a0.z, a1.z);
            split_store2(sBh, sBl, n0 + 2, kc0 + 2, a2.z, a3.z);
            split_store2(sBh, sBl, n0 + 3, kc0,     a0.w, a1.w);
            split_store2(sBh, sBl, n0 + 3, kc0 + 2, a2.w, a3.w);
        }
        __syncthreads();

        // ---- MMA: 4 k-steps of 16; 3 passes fused per step ----
        #pragma unroll
        for (int ks = 0; ks < 4; ks++) {
            int kb = ks * 16 + cq * 2;
            uint32_t Ah[2][4], Al[2][4];
            #pragma unroll
            for (int t = 0; t < 2; t++) {
                int r = wm * 32 + t * 16 + g;
                Ah[t][0] = lds_pair(sAh, r,     kb);
                Ah[t][1] = lds_pair(sAh, r + 8, kb);
                Ah[t][2] = lds_pair(sAh, r,     kb + 8);
                Ah[t][3] = lds_pair(sAh, r + 8, kb + 8);
                Al[t][0] = lds_pair(sAl, r,     kb);
                Al[t][1] = lds_pair(sAl, r + 8, kb);
                Al[t][2] = lds_pair(sAl, r,     kb + 8);
                Al[t][3] = lds_pair(sAl, r + 8, kb + 8);
            }
            #pragma unroll
            for (int nt = 0; nt < 8; nt++) {
                int nr = wn * 64 + nt * 8 + g;
                uint32_t bh0 = lds_pair(sBh, nr, kb);
                uint32_t bh1 = lds_pair(sBh, nr, kb + 8);
                uint32_t bl0 = lds_pair(sBl, nr, kb);
                uint32_t bl1 = lds_pair(sBl, nr, kb + 8);
                #pragma unroll
                for (int t = 0; t < 2; t++) {
                    mma16816(acc[t][nt], Ah[t], bh0, bh1);
                    mma16816(acc[t][nt], Ah[t], bl0, bl1);
                    mma16816(acc[t][nt], Al[t], bh0, bh1);
                }
            }
        }
        __syncthreads();
    }

    // ---- epilogue: scale by dinv, store to g_hs ----
    float* hsf = (float*)g_hs;
    #pragma unroll
    for (int t = 0; t < 2; t++) {
        int r0 = m0 + wm * 32 + t * 16 + g;
        int r1 = r0 + 8;
        #pragma unroll
        for (int nt = 0; nt < 8; nt++) {
            int col = wn * 64 + nt * 8 + cq * 2;
            if (r0 < NNODES) {
                float di = g_dinv[r0];
                *(float2*)&hsf[(size_t)r0 * GN + col] =
                    make_float2(acc[t][nt][0] * di, acc[t][nt][1] * di);
            }
            if (r1 < NNODES) {
                float di = g_dinv[r1];
                *(float2*)&hsf[(size_t)r1 * GN + col] =
                    make_float2(acc[t][nt][2] * di, acc[t][nt][3] * di);
            }
        }
    }
}

// warp-per-node gather: out = dinv[n] * (hs[n] + sum_{src in-edges} hs[src]) + bias
__global__ void __launch_bounds__(256) gather_kernel(const float* __restrict__ bmu,
                                                     const float* __restrict__ bls,
                                                     float* __restrict__ out) {
    int gw = (blockIdx.x * blockDim.x + threadIdx.x) >> 5;
    if (gw >= NNODES) return;
    int lane = threadIdx.x & 31;
    int n = gw;
    float din  = g_dinv[n];
    int begin  = g_off[n];
    int cn     = g_cnt[n];

    float4 acc = g_hs[(size_t)n * 32 + lane];
    for (int base = 0; base < cn; base += 32) {
        int idx = base + lane;
        int sp = (idx < cn) ? g_perm[begin + idx] : 0;
        int m = cn - base; if (m > 32) m = 32;
        for (int j = 0; j < m; j++) {
            int s = __shfl_sync(0xffffffffu, sp, j);
            float4 v = g_hs[(size_t)s * 32 + lane];
            acc.x += v.x; acc.y += v.y; acc.z += v.z; acc.w += v.w;
        }
    }
    float4* out4 = (float4*)out;
    if (lane < 16) {
        float4 bb = ((const float4*)bmu)[lane];
        out4[(size_t)n * 16 + lane] =
            make_float4(acc.x * din + bb.x, acc.y * din + bb.y,
                        acc.z * din + bb.z, acc.w * din + bb.w);
    } else {
        float4 bb = ((const float4*)bls)[lane - 16];
        out4[(size_t)NNODES * 16 + (size_t)n * 16 + (lane - 16)] =
            make_float4(acc.x * din + bb.x, acc.y * din + bb.y,
                        acc.z * din + bb.z, acc.w * din + bb.w);
    }
}

// ---------------- launch ----------------
extern "C" void kernel_launch(void* const* d_in, const int* in_sizes, int n_in,
                              void* d_out, int out_size) {
    const float* x   = (const float*)d_in[0];
    const int*   ew  = (const int*)d_in[1];
    const float* Wmu = (const float*)d_in[2];
    const float* bmu = (const float*)d_in[3];
    const float* Wls = (const float*)d_in[4];
    const float* bls = (const float*)d_in[5];
    float*       out = (float*)d_out;

    const int NB_N  = (NNODES + 255) / 256;
    const int NB_E  = (NEDGES + 255) / 256;
    const int NB_SC = (NNODES + 1023) / 1024;
    const int NB_GM = (NNODES + MT - 1) / MT;       // 782
    const int NB_GA = (NNODES * 32 + 255) / 256;
    const int SMEM  = 4 * TILE_BYTES;               // 73728

    cudaFuncSetAttribute(gemm_mma_kernel,
                         cudaFuncAttributeMaxDynamicSharedMemorySize, SMEM);

    probe_kernel<<<1, 256>>>(ew);
    zero_cnt_kernel<<<NB_N, 256>>>();
    count_kernel<<<NB_E, 256>>>(ew);
    scan_block_kernel<<<NB_SC, 1024>>>();
    scan_bsums_kernel<<<1, 128>>>(NB_SC);
    scan_finalize_kernel<<<NB_N, 256>>>();
    gemm_mma_kernel<<<NB_GM, 256, SMEM>>>(x, Wmu, Wls);
    build_perm_kernel<<<NB_E, 256>>>(ew);
    gather_kernel<<<NB_GA, 256>>>(bmu, bls, out);
}

// round 8
// speedup vs baseline: 1.2387x; 1.0690x over previous
#include <cuda_runtime.h>
#include <cuda_bf16.h>
#include <cuda_fp16.h>
#include <stdint.h>

#define NNODES 100000
#define NEDGES 1600000
#define INCH   256
#define OUTCH  64
#define GN     128   // combined output cols (mu | logstd)

// ---------------- static scratch (no allocations allowed) ----------------
__device__ int    g_cnt[NNODES];
__device__ int    g_off[NNODES];
__device__ int    g_cur[NNODES];
__device__ float  g_dinv[NNODES];
__device__ int    g_perm[NEDGES];
__device__ int    g_bsum[128];
__device__ int    g_is64;
// hs in fp16: per node 128 halves = 256B; lane's uint2 = halves [lane*4 .. lane*4+3]
__device__ __align__(16) uint2 g_hs16[NNODES * 32];

// ---------------- edge index access helpers ----------------
__device__ __forceinline__ int clampN(int v) {
    v = v < 0 ? 0 : v;
    return v >= NNODES ? NNODES - 1 : v;
}
__device__ __forceinline__ int load_src(const int* w, int is64, int e) {
    return clampN(is64 ? w[2 * e] : w[e]);
}
__device__ __forceinline__ int load_dst(const int* w, int is64, int e) {
    return clampN(is64 ? w[2 * (NEDGES + e)] : w[NEDGES + e]);
}

// ---------------- kernels ----------------
__global__ void probe_kernel(const int* __restrict__ w) {
    int tid = threadIdx.x;
    int v = w[2 * tid + 1];
    int allzero = __syncthreads_and(v == 0);
    if (tid == 0) g_is64 = allzero ? 1 : 0;
}

__global__ void zero_cnt_kernel() {
    int i = blockIdx.x * blockDim.x + threadIdx.x;
    if (i < NNODES) g_cnt[i] = 0;
}

__global__ void count_kernel(const int* __restrict__ w) {
    int e = blockIdx.x * blockDim.x + threadIdx.x;
    if (e < NEDGES) atomicAdd(&g_cnt[load_dst(w, g_is64, e)], 1);
}

__global__ void __launch_bounds__(1024) scan_block_kernel() {
    int tid = threadIdx.x;
    int i = blockIdx.x * 1024 + tid;
    int v = (i < NNODES) ? g_cnt[i] : 0;
    int lane = tid & 31, w = tid >> 5;
    int x = v;
    #pragma unroll
    for (int d = 1; d < 32; d <<= 1) {
        int y = __shfl_up_sync(0xffffffffu, x, d);
        if (lane >= d) x += y;
    }
    __shared__ int wsum[32];
    if (lane == 31) wsum[w] = x;
    __syncthreads();
    if (w == 0) {
        int y = wsum[lane];
        #pragma unroll
        for (int d = 1; d < 32; d <<= 1) {
            int z = __shfl_up_sync(0xffffffffu, y, d);
            if (lane >= d) y += z;
        }
        wsum[lane] = y;
    }
    __syncthreads();
    int incl = x + ((w > 0) ? wsum[w - 1] : 0);
    if (i < NNODES) g_off[i] = incl - v;
    if (tid == 1023) g_bsum[blockIdx.x] = incl;
}

__global__ void scan_bsums_kernel(int nb) {
    __shared__ int s[128];
    int tid = threadIdx.x;
    if (tid < nb) s[tid] = g_bsum[tid];
    __syncthreads();
    if (tid == 0) {
        int acc = 0;
        for (int b = 0; b < nb; b++) { int t = s[b]; s[b] = acc; acc += t; }
    }
    __syncthreads();
    if (tid < nb) g_bsum[tid] = s[tid];
}

__global__ void scan_finalize_kernel() {
    int i = blockIdx.x * blockDim.x + threadIdx.x;
    if (i < NNODES) {
        int o = g_off[i] + g_bsum[i >> 10];
        g_off[i] = o;
        g_cur[i] = o;
        g_dinv[i] = rsqrtf((float)(g_cnt[i] + 1));
    }
}

__global__ void build_perm_kernel(const int* __restrict__ w) {
    int e = blockIdx.x * blockDim.x + threadIdx.x;
    if (e < NEDGES) {
        int is64 = g_is64;
        int src = load_src(w, is64, e);
        int dst = load_dst(w, is64, e);
        int p = atomicAdd(&g_cur[dst], 1);
        if (p >= 0 && p < NEDGES) g_perm[p] = src;
    }
}

// ---------------- HMMA (mma.sync) dual GEMM ----------------
// hs[n][0:64] = (x@W_mu)*dinv[n], hs[n][64:128] = (x@W_logstd)*dinv[n]
// bf16 hi/lo split: D = Ah*Bh + Ah*Bl + Al*Bh  (fp32 accumulate in registers)
#define MT 128
#define KC 64
#define NCHUNK (INCH / KC)   // 4
#define ASTR 72              // bf16 elements per SMEM row (144B: 4-bank shift/row -> conflict-free)
#define TILE_BYTES (128 * ASTR * 2)   // 18432

__device__ __forceinline__ uint32_t bf2pack(float a, float b) {
    __nv_bfloat162 p = __nv_bfloat162(__float2bfloat16_rn(a), __float2bfloat16_rn(b));
    return *(uint32_t*)&p;
}
// store hi & lo pair (cols c, c+1) for row r
__device__ __forceinline__ void split_store2(char* hi, char* lo, int r, int c,
                                             float a, float b) {
    float ha = __bfloat162float(__float2bfloat16_rn(a));
    float hb = __bfloat162float(__float2bfloat16_rn(b));
    *(uint32_t*)(hi + r * (ASTR * 2) + c * 2) = bf2pack(a, b);
    *(uint32_t*)(lo + r * (ASTR * 2) + c * 2) = bf2pack(a - ha, b - hb);
}
__device__ __forceinline__ uint32_t lds_pair(const char* base, int r, int c) {
    return *(const uint32_t*)(base + r * (ASTR * 2) + c * 2);
}
__device__ __forceinline__ void mma16816(float* d, const uint32_t* a, uint32_t b0, uint32_t b1) {
    asm volatile(
        "mma.sync.aligned.m16n8k16.row.col.f32.bf16.bf16.f32 "
        "{%0,%1,%2,%3}, {%4,%5,%6,%7}, {%8,%9}, {%0,%1,%2,%3};"
        : "+f"(d[0]), "+f"(d[1]), "+f"(d[2]), "+f"(d[3])
        : "r"(a[0]), "r"(a[1]), "r"(a[2]), "r"(a[3]), "r"(b0), "r"(b1));
}

__global__ void __launch_bounds__(256) gemm_mma_kernel(const float* __restrict__ x,
                                                       const float* __restrict__ Wmu,
                                                       const float* __restrict__ Wls) {
    extern __shared__ char dsm[];
    char* sAh = dsm;
    char* sAl = dsm + TILE_BYTES;
    char* sBh = dsm + 2 * TILE_BYTES;
    char* sBl = dsm + 3 * TILE_BYTES;

    int tid  = threadIdx.x;
    int wid  = tid >> 5, lane = tid & 31;
    int wm   = wid & 3;          // m strip: rows wm*32 .. +31
    int wn   = wid >> 2;         // n strip: cols wn*64 .. +63
    int g    = lane >> 2;        // 0..7
    int cq   = lane & 3;         // 0..3
    int m0   = blockIdx.x * MT;

    float acc[2][8][4];
    #pragma unroll
    for (int t = 0; t < 2; t++)
        #pragma unroll
        for (int n = 0; n < 8; n++)
            #pragma unroll
            for (int q = 0; q < 4; q++) acc[t][n][q] = 0.f;

    for (int c0 = 0; c0 < NCHUNK; c0++) {
        int k0 = c0 * KC;
        // ---- A chunk: row tid/2, half (tid&1)*32 (8 float4) ----
        {
            int r = tid >> 1, h = (tid & 1) * 32;
            int row = m0 + r;
            bool valid = row < NNODES;
            const float4* xr = (const float4*)&x[(size_t)(valid ? row : 0) * INCH + k0 + h];
            #pragma unroll
            for (int j = 0; j < 8; j++) {
                float4 v = valid ? xr[j] : make_float4(0.f, 0.f, 0.f, 0.f);
                split_store2(sAh, sAl, r, h + j * 4,     v.x, v.y);
                split_store2(sAh, sAl, r, h + j * 4 + 2, v.z, v.w);
            }
        }
        // ---- B chunk: B[n][k] = W[k0+k][n]; 4x4 transpose blocks ----
        #pragma unroll
        for (int it = 0; it < 2; it++) {
            int w  = tid + it * 256;        // 0..511
            int nq = w >> 4, kq = w & 15;
            int n0 = nq * 4, kc0 = kq * 4;
            const float* Wp = (n0 < OUTCH) ? Wmu : Wls;
            int ncol = (n0 < OUTCH) ? n0 : n0 - OUTCH;
            float4 a0 = *(const float4*)&Wp[(size_t)(k0 + kc0 + 0) * OUTCH + ncol];
            float4 a1 = *(const float4*)&Wp[(size_t)(k0 + kc0 + 1) * OUTCH + ncol];
            float4 a2 = *(const float4*)&Wp[(size_t)(k0 + kc0 + 2) * OUTCH + ncol];
            float4 a3 = *(const float4*)&Wp[(size_t)(k0 + kc0 + 3) * OUTCH + ncol];
            split_store2(sBh, sBl, n0 + 0, kc0,     a0.x, a1.x);
            split_store2(sBh, sBl, n0 + 0, kc0 + 2, a2.x, a3.x);
            split_store2(sBh, sBl, n0 + 1, kc0,     a0.y, a1.y);
            split_store2(sBh, sBl, n0 + 1, kc0 + 2, a2.y, a3.y);
            split_store2(sBh, sBl, n0 + 2, kc0,     a0.z, a1.z);
            split_store2(sBh, sBl, n0 + 2, kc0 + 2, a2.z, a3.z);
            split_store2(sBh, sBl, n0 + 3, kc0,     a0.w, a1.w);
            split_store2(sBh, sBl, n0 + 3, kc0 + 2, a2.w, a3.w);
        }
        __syncthreads();

        // ---- MMA: 4 k-steps of 16; 3 passes fused per step ----
        #pragma unroll
        for (int ks = 0; ks < 4; ks++) {
            int kb = ks * 16 + cq * 2;
            uint32_t Ah[2][4], Al[2][4];
            #pragma unroll
            for (int t = 0; t < 2; t++) {
                int r = wm * 32 + t * 16 + g;
                Ah[t][0] = lds_pair(sAh, r,     kb);
                Ah[t][1] = lds_pair(sAh, r + 8, kb);
                Ah[t][2] = lds_pair(sAh, r,     kb + 8);
                Ah[t][3] = lds_pair(sAh, r + 8, kb + 8);
                Al[t][0] = lds_pair(sAl, r,     kb);
                Al[t][1] = lds_pair(sAl, r + 8, kb);
                Al[t][2] = lds_pair(sAl, r,     kb + 8);
                Al[t][3] = lds_pair(sAl, r + 8, kb + 8);
            }
            #pragma unroll
            for (int nt = 0; nt < 8; nt++) {
                int nr = wn * 64 + nt * 8 + g;
                uint32_t bh0 = lds_pair(sBh, nr, kb);
                uint32_t bh1 = lds_pair(sBh, nr, kb + 8);
                uint32_t bl0 = lds_pair(sBl, nr, kb);
                uint32_t bl1 = lds_pair(sBl, nr, kb + 8);
                #pragma unroll
                for (int t = 0; t < 2; t++) {
                    mma16816(acc[t][nt], Ah[t], bh0, bh1);
                    mma16816(acc[t][nt], Ah[t], bl0, bl1);
                    mma16816(acc[t][nt], Al[t], bh0, bh1);
                }
            }
        }
        __syncthreads();
    }

    // ---- epilogue: scale by dinv, store fp16 to g_hs16 ----
    __half2* hs2 = (__half2*)g_hs16;      // [node][64] half2
    #pragma unroll
    for (int t = 0; t < 2; t++) {
        int r0 = m0 + wm * 32 + t * 16 + g;
        int r1 = r0 + 8;
        #pragma unroll
        for (int nt = 0; nt < 8; nt++) {
            int col = wn * 64 + nt * 8 + cq * 2;
            if (r0 < NNODES) {
                float di = g_dinv[r0];
                hs2[(size_t)r0 * 64 + (col >> 1)] =
                    __floats2half2_rn(acc[t][nt][0] * di, acc[t][nt][1] * di);
            }
            if (r1 < NNODES) {
                float di = g_dinv[r1];
                hs2[(size_t)r1 * 64 + (col >> 1)] =
                    __floats2half2_rn(acc[t][nt][2] * di, acc[t][nt][3] * di);
            }
        }
    }
}

// warp-per-node gather: out = dinv[n] * (hs[n] + sum_{src in-edges} hs[src]) + bias
__global__ void __launch_bounds__(256) gather_kernel(const float* __restrict__ bmu,
                                                     const float* __restrict__ bls,
                                                     float* __restrict__ out) {
    int gw = (blockIdx.x * blockDim.x + threadIdx.x) >> 5;
    if (gw >= NNODES) return;
    int lane = threadIdx.x & 31;
    int n = gw;
    float din  = g_dinv[n];
    int begin  = g_off[n];
    int cn     = g_cnt[n];

    // self-loop term
    uint2 v0 = g_hs16[(size_t)n * 32 + lane];
    float2 p0 = __half22float2(*(__half2*)&v0.x);
    float2 p1 = __half22float2(*(__half2*)&v0.y);
    float4 acc = make_float4(p0.x, p0.y, p1.x, p1.y);

    for (int base = 0; base < cn; base += 32) {
        int idx = base + lane;
        int sp = (idx < cn) ? g_perm[begin + idx] : 0;
        int m = cn - base; if (m > 32) m = 32;
        for (int j = 0; j < m; j++) {
            int s = __shfl_sync(0xffffffffu, sp, j);
            uint2 v = g_hs16[(size_t)s * 32 + lane];
            float2 q0 = __half22float2(*(__half2*)&v.x);
            float2 q1 = __half22float2(*(__half2*)&v.y);
            acc.x += q0.x; acc.y += q0.y; acc.z += q1.x; acc.w += q1.y;
        }
    }
    float4* out4 = (float4*)out;
    if (lane < 16) {
        float4 bb = ((const float4*)bmu)[lane];
        out4[(size_t)n * 16 + lane] =
            make_float4(acc.x * din + bb.x, acc.y * din + bb.y,
                        acc.z * din + bb.z, acc.w * din + bb.w);
    } else {
        float4 bb = ((const float4*)bls)[lane - 16];
        out4[(size_t)NNODES * 16 + (size_t)n * 16 + (lane - 16)] =
            make_float4(acc.x * din + bb.x, acc.y * din + bb.y,
                        acc.z * din + bb.z, acc.w * din + bb.w);
    }
}

// ---------------- launch ----------------
extern "C" void kernel_launch(void* const* d_in, const int* in_sizes, int n_in,
                              void* d_out, int out_size) {
    const float* x   = (const float*)d_in[0];
    const int*   ew  = (const int*)d_in[1];
    const float* Wmu = (const float*)d_in[2];
    const float* bmu = (const float*)d_in[3];
    const float* Wls = (const float*)d_in[4];
    const float* bls = (const float*)d_in[5];
    float*       out = (float*)d_out;

    const int NB_N  = (NNODES + 255) / 256;
    const int NB_E  = (NEDGES + 255) / 256;
    const int NB_SC = (NNODES + 1023) / 1024;
    const int NB_GM = (NNODES + MT - 1) / MT;       // 782
    const int NB_GA = (NNODES * 32 + 255) / 256;
    const int SMEM  = 4 * TILE_BYTES;               // 73728

    cudaFuncSetAttribute(gemm_mma_kernel,
                         cudaFuncAttributeMaxDynamicSharedMemorySize, SMEM);

    probe_kernel<<<1, 256>>>(ew);
    zero_cnt_kernel<<<NB_N, 256>>>();
    count_kernel<<<NB_E, 256>>>(ew);
    scan_block_kernel<<<NB_SC, 1024>>>();
    scan_bsums_kernel<<<1, 128>>>(NB_SC);
    scan_finalize_kernel<<<NB_N, 256>>>();
    gemm_mma_kernel<<<NB_GM, 256, SMEM>>>(x, Wmu, Wls);
    build_perm_kernel<<<NB_E, 256>>>(ew);
    gather_kernel<<<NB_GA, 256>>>(bmu, bls, out);
}